// round 11
// baseline (speedup 1.0000x reference)
#include <cuda_runtime.h>
#include <math.h>

typedef unsigned long long ull;

#define BB   32
#define CIN  64
#define TT   512
#define FF   256
#define GG   8
#define HH   512
#define G4   2048
#define NCLS 50
#define RNB  128
#define NSLOT (TT + 2)
#define PSZ  (8 * 16 * 33)          // partials (floats)

// ------------------------- scratch -----------------------------------------
__device__ float   g_conv[BB * FF * TT];
__device__ float   g_xt[BB * TT * FF];
__device__ float   g_xp[BB * TT * G4];
__device__ float   g_hb1[2][BB * HH];    // [parity][b*HH + unit]
__device__ float   g_hb2[2][BB * HH];
__device__ float   g_hb3[2][BB * HH];
__device__ float   g_feat[BB * HH];
__device__ float2  g_stat[BB * GG];
__device__ unsigned g_cnt;
__device__ unsigned g_gen;

// ------------------------- helpers -----------------------------------------
__device__ __forceinline__ void fma2(ull& d, ull a, ull b) {
    asm("fma.rn.f32x2 %0, %1, %2, %0;" : "+l"(d) : "l"(a), "l"(b));
}
union UF2 { ull u; float2 f; };
#define CP_ASYNC16(dst_u32, src_ptr) \
    asm volatile("cp.async.cg.shared.global [%0], [%1], 16;" \
                 :: "r"(dst_u32), "l"(src_ptr))
#define CP_COMMIT() asm volatile("cp.async.commit_group;")
#define CP_WAIT(n)  asm volatile("cp.async.wait_group " #n ";" ::: "memory")

// ------------------------------- conv1d ------------------------------------
#define CONV_SMEM ((64 * 136 + 8 * 64 * 9) * 4)
__global__ __launch_bounds__(256) void conv_kernel(
    const float* __restrict__ x, const float* __restrict__ w)
{
    extern __shared__ float sm[];
    float* xs = sm;
    float* ws = sm + 64 * 136;
    const int b   = blockIdx.y;
    const int t0  = blockIdx.x * 128;
    const int tid = threadIdx.x;

    for (int i = tid; i < 64 * 136; i += 256) {
        int c = i / 136, j = i - c * 136;
        int t = t0 - 4 + j;
        xs[i] = (t >= 0 && t < TT) ? x[(b * CIN + c) * TT + t] : 0.f;
    }
    const int lane = tid & 31;
    const int wf   = tid >> 5;
    const int tl   = lane * 4;

    for (int fc = 0; fc < FF; fc += 8) {
        __syncthreads();
        for (int i = tid; i < 8 * 64 * 9; i += 256)
            ws[i] = w[fc * 64 * 9 + i];
        __syncthreads();
        const int f = fc + wf;
        float a0 = 0.f, a1 = 0.f, a2 = 0.f, a3 = 0.f;
        for (int c = 0; c < 64; ++c) {
            const float* xr = &xs[c * 136 + tl];
            const float* wr = &ws[(wf * 64 + c) * 9];
            float4 p0 = *(const float4*)(xr);
            float4 p1 = *(const float4*)(xr + 4);
            float4 p2 = *(const float4*)(xr + 8);
            float xv[12] = {p0.x, p0.y, p0.z, p0.w, p1.x, p1.y, p1.z, p1.w,
                            p2.x, p2.y, p2.z, p2.w};
#pragma unroll
            for (int k = 0; k < 9; ++k) {
                float wk = wr[k];
                a0 += wk * xv[k];
                a1 += wk * xv[k + 1];
                a2 += wk * xv[k + 2];
                a3 += wk * xv[k + 3];
            }
        }
        *(float4*)&g_conv[(b * FF + f) * TT + t0 + tl] =
            make_float4(a0, a1, a2, a3);
    }
}

// ------------------------------ groupnorm -----------------------------------
__global__ __launch_bounds__(256) void gn_stats_kernel()
{
    const int b = blockIdx.x >> 3, g = blockIdx.x & 7;
    __shared__ float ssum[256], ssq[256];
    const int tid = threadIdx.x;
    const float* base = g_conv + (b * FF + g * 32) * TT;
    float s = 0.f, q = 0.f;
    for (int i = tid; i < 32 * TT; i += 256) {
        float v = base[i];
        s += v; q += v * v;
    }
    ssum[tid] = s; ssq[tid] = q;
    __syncthreads();
    for (int o = 128; o > 0; o >>= 1) {
        if (tid < o) { ssum[tid] += ssum[tid + o]; ssq[tid] += ssq[tid + o]; }
        __syncthreads();
    }
    if (tid == 0) {
        float mean = ssum[0] * (1.f / 16384.f);
        float var  = ssq[0] * (1.f / 16384.f) - mean * mean;
        g_stat[b * GG + g] = make_float2(mean, rsqrtf(var + 1e-5f));
    }
}

__global__ __launch_bounds__(256) void gn_apply_kernel(
    const float* __restrict__ gamma, const float* __restrict__ beta)
{
    __shared__ float tile[32][33];
    const int b  = blockIdx.z;
    const int f0 = blockIdx.y * 32;
    const int t0 = blockIdx.x * 32;
    const int tx = threadIdx.x & 31, ty = threadIdx.x >> 5;
#pragma unroll
    for (int j = 0; j < 4; ++j) {
        int f = f0 + ty + j * 8;
        float2 st = g_stat[b * GG + (f >> 5)];
        float v = g_conv[(b * FF + f) * TT + t0 + tx];
        v = (v - st.x) * st.y * gamma[f] + beta[f];
        tile[ty + j * 8][tx] = fmaxf(v, 0.f);
    }
    __syncthreads();
#pragma unroll
    for (int j = 0; j < 4; ++j) {
        int t = t0 + ty + j * 8;
        g_xt[(b * TT + t) * FF + f0 + tx] = tile[tx][ty + j * 8];
    }
}

// --------------------- projection GEMM (layer 1) ----------------------------
__global__ __launch_bounds__(256) void gemm_kernel(
    const float* __restrict__ A, const float* __restrict__ Bm,
    const float* __restrict__ bias, float* __restrict__ C, int Ka)
{
    __shared__ float As[16][64];
    __shared__ float Bs[16][64];
    const int bm = blockIdx.y * 64, bn = blockIdx.x * 64;
    const int tid = threadIdx.x;
    const int lm  = tid >> 2;
    const int lk4 = (tid & 3) * 4;
    const int tm  = (tid & 15) * 4;
    const int tn  = (tid >> 4) * 4;

    float acc[4][4];
#pragma unroll
    for (int i = 0; i < 4; ++i)
#pragma unroll
        for (int j = 0; j < 4; ++j) acc[i][j] = 0.f;

    for (int ko = 0; ko < Ka; ko += 16) {
        float4 av = *(const float4*)&A[(bm + lm) * Ka + ko + lk4];
        float4 bv = *(const float4*)&Bm[(bn + lm) * Ka + ko + lk4];
        __syncthreads();
        As[lk4 + 0][lm] = av.x; As[lk4 + 1][lm] = av.y;
        As[lk4 + 2][lm] = av.z; As[lk4 + 3][lm] = av.w;
        Bs[lk4 + 0][lm] = bv.x; Bs[lk4 + 1][lm] = bv.y;
        Bs[lk4 + 2][lm] = bv.z; Bs[lk4 + 3][lm] = bv.w;
        __syncthreads();
#pragma unroll
        for (int k = 0; k < 16; ++k) {
            float4 a4 = *(const float4*)&As[k][tm];
            float4 b4 = *(const float4*)&Bs[k][tn];
            float am[4] = {a4.x, a4.y, a4.z, a4.w};
            float bn4[4] = {b4.x, b4.y, b4.z, b4.w};
#pragma unroll
            for (int i = 0; i < 4; ++i)
#pragma unroll
                for (int j = 0; j < 4; ++j) acc[i][j] += am[i] * bn4[j];
        }
    }
#pragma unroll
    for (int i = 0; i < 4; ++i) {
        int row = bm + tm + i;
#pragma unroll
        for (int j = 0; j < 4; ++j)
            C[row * G4 + bn + tn + j] = acc[i][j] + bias[bn + tn + j];
    }
}

// ----------------------- zero h buffers -------------------------------------
__global__ void zero_h_kernel()
{
    int i = blockIdx.x * 256 + threadIdx.x;   // grid 128 -> 32768 (both parities)
    ((float*)g_hb1)[i] = 0.f;
    ((float*)g_hb2)[i] = 0.f;
    ((float*)g_hb3)[i] = 0.f;
}

// ------------------------- grid barrier (R7, proven) ------------------------
__device__ __forceinline__ void grid_bar()
{
    __syncthreads();
    if (threadIdx.x == 0) {
        unsigned gen = *(volatile unsigned*)&g_gen;
        __threadfence();
        if (atomicAdd(&g_cnt, 1u) == RNB - 1) {
            g_cnt = 0;
            __threadfence();
            atomicAdd(&g_gen, 1u);
        } else {
            while (*(volatile unsigned*)&g_gen == gen) __nanosleep(32);
        }
    }
    __syncthreads();
}

// ---- per-thread GEMM: 8 rows x 1 batch, warp-uniform weights, 2-deep pf ----
// acc[i]: i<4 -> gate 2rg unit i ; i>=4 -> gate 2rg+1 unit i-4.
__device__ __forceinline__ void gphase(ull acc[8],
    const float* __restrict__ w0, const float* __restrict__ w1,
    const float* hrow, int swz, int ng)
{
#pragma unroll
    for (int i = 0; i < 8; ++i) acc[i] = 0ull;
    ulonglong2 wa[8], wb[8];
#pragma unroll
    for (int i = 0; i < 4; ++i) {
        wa[i]     = __ldg((const ulonglong2*)(w0 + i * 512));
        wa[4 + i] = __ldg((const ulonglong2*)(w1 + i * 512));
        wb[i]     = __ldg((const ulonglong2*)(w0 + i * 512 + 4));
        wb[4 + i] = __ldg((const ulonglong2*)(w1 + i * 512 + 4));
    }
    for (int l = 0; l < ng; l += 2) {
        // iter l with wa
        {
            const int lp = ((l & ~7) | ((l & 7) ^ swz)) * 4;
            ulonglong2 hv = *(const ulonglong2*)(hrow + lp);
#pragma unroll
            for (int i = 0; i < 8; ++i) {
                fma2(acc[i], wa[i].x, hv.x);
                fma2(acc[i], wa[i].y, hv.y);
            }
            const int nx = (l + 2 < ng) ? (l + 2) : 0;
#pragma unroll
            for (int i = 0; i < 4; ++i) {
                wa[i]     = __ldg((const ulonglong2*)(w0 + i * 512 + nx * 4));
                wa[4 + i] = __ldg((const ulonglong2*)(w1 + i * 512 + nx * 4));
            }
        }
        // iter l+1 with wb
        {
            const int l1 = l + 1;
            const int lp = ((l1 & ~7) | ((l1 & 7) ^ swz)) * 4;
            ulonglong2 hv = *(const ulonglong2*)(hrow + lp);
#pragma unroll
            for (int i = 0; i < 8; ++i) {
                fma2(acc[i], wb[i].x, hv.x);
                fma2(acc[i], wb[i].y, hv.y);
            }
            const int nx = (l1 + 2 < ng) ? (l1 + 2) : 0;
#pragma unroll
            for (int i = 0; i < 4; ++i) {
                wb[i]     = __ldg((const ulonglong2*)(w0 + i * 512 + nx * 4));
                wb[4 + i] = __ldg((const ulonglong2*)(w1 + i * 512 + nx * 4));
            }
        }
    }
}

// partials layout: [ks 8][row 16][b 32 pad33]; row = (2rg + (i>>2))*4 + (i&3)
__device__ __forceinline__ void store_part(float* pl, ull acc[8],
                                           int ks, int rg, int bp)
{
#pragma unroll
    for (int i = 0; i < 8; ++i) {
        UF2 t; t.u = acc[i];
        int row = (2 * rg + (i >> 2)) * 4 + (i & 3);
        pl[(ks * 16 + row) * 33 + bp] = t.f.x + t.f.y;
    }
}

__device__ __forceinline__ float4 cell_sum(const float* pl, int cu, int cb)
{
    float4 s = make_float4(0.f, 0.f, 0.f, 0.f);
#pragma unroll
    for (int k = 0; k < 8; ++k) {
        const float* pb = pl + (k * 16) * 33 + cb;
        s.x += pb[(0  + cu) * 33];
        s.y += pb[(4  + cu) * 33];
        s.z += pb[(8  + cu) * 33];
        s.w += pb[(12 + cu) * 33];
    }
    return s;
}

__device__ __forceinline__ float lstm_cell(float4 g, float& c)
{
    float ig = 1.f / (1.f + __expf(-g.x));
    float fg = 1.f / (1.f + __expf(-g.y));
    float gv = tanhf(g.z);
    float og = 1.f / (1.f + __expf(-g.w));
    c = fg * c + ig * gv;
    return og * tanhf(c);
}

// ------------------- fused 3-layer wavefront recurrence ---------------------
// smem: buf1/2/3 [32 b][512 k] (64KB each, per-b octet swizzle) + partials
#define FSMEM ((3 * HH * BB + PSZ) * 4)
__global__ __launch_bounds__(512, 1) void fused_rec_kernel(
    const float* __restrict__ xp,
    const float* __restrict__ whh1,
    const float* __restrict__ wih2, const float* __restrict__ whh2,
    const float* __restrict__ b2,
    const float* __restrict__ wih3, const float* __restrict__ whh3,
    const float* __restrict__ b3)
{
    extern __shared__ float sm[];
    float* buf1 = sm;
    float* buf2 = sm + HH * BB;
    float* buf3 = sm + 2 * HH * BB;
    float* part = sm + 3 * HH * BB;

    const int tid = threadIdx.x;
    const int ks  = tid >> 6;          // 0..7  (k-slice; warp-pair granularity)
    const int rg  = (tid >> 5) & 1;    // gate-pair
    const int bp  = tid & 31;          // batch (lane)
    const int swz = bp & 7;
    const int u4  = blockIdx.x * 4;

    // weight row bases: rows (2rg)*HH+u4.. and (2rg+1)*HH+u4..
    const int g0r = (2 * rg) * HH + u4;
    const int g1r = (2 * rg + 1) * HH + u4;
    const float* a_w0 = whh1 + g0r * 512 + ks * 64;
    const float* a_w1 = whh1 + g1r * 512 + ks * 64;
    const float* wBm  = (ks < 4) ? wih2 : whh2;
    const float* wCm  = (ks < 4) ? wih3 : whh3;
    const int koff = (ks & 3) * 128;
    const float* b_w0 = wBm + g0r * 512 + koff;
    const float* b_w1 = wBm + g1r * 512 + koff;
    const float* c_w0 = wCm + g0r * 512 + koff;
    const float* c_w1 = wCm + g1r * 512 + koff;

    // h smem row bases (row = this lane's batch)
    const float* hA = buf1 + bp * 512 + ks * 64;
    const float* hB = ((ks < 4) ? buf1 : buf2) + bp * 512 + koff;
    const float* hC = ((ks < 4) ? buf2 : buf3) + bp * 512 + koff;

    // cell mapping (tid < 128)
    const int cu = tid >> 5;
    const int cb = tid & 31;
    const int cunit = u4 + cu;
    float c1 = 0.f, c2 = 0.f, c3 = 0.f, h3sum = 0.f;
    float bias2[4], bias3[4];
    if (tid < 128) {
#pragma unroll
        for (int g = 0; g < 4; ++g) {
            bias2[g] = b2[g * HH + cunit];
            bias3[g] = b3[g * HH + cunit];
        }
    }

    // staging: thread covers (b = bseg*8+j, granule k4c) for each buffer
    const int k4c  = tid & 127;
    const int bseg = tid >> 7;
    const unsigned sb1 = (unsigned)__cvta_generic_to_shared(buf1);
    const unsigned sb2 = (unsigned)__cvta_generic_to_shared(buf2);
    const unsigned sb3 = (unsigned)__cvta_generic_to_shared(buf3);

    ull acc[8];

    for (int slot = 0; slot < NSLOT; ++slot) {
        const int rdp = (slot + 1) & 1;
        const int wrp = slot & 1;
        const bool v1 = slot < TT;
        const bool v2 = (slot >= 1) && (slot < TT + 1);
        const bool v3 = slot >= 2;

        // ---- async stage h1/h2/h3 (one commit group per buffer) ----
        {
            const char* s1 = (const char*)(g_hb1[rdp]);
            const char* s2 = (const char*)(g_hb2[rdp]);
            const char* s3 = (const char*)(g_hb3[rdp]);
#pragma unroll
            for (int j = 0; j < 8; ++j) {
                int b = bseg * 8 + j;
                unsigned doff = (unsigned)((b * 128 +
                    ((k4c & ~7) | ((k4c & 7) ^ (b & 7)))) * 16);
                unsigned soff = (unsigned)((b * 128 + k4c) * 16);
                CP_ASYNC16(sb1 + doff, s1 + soff);
            }
            CP_COMMIT();
#pragma unroll
            for (int j = 0; j < 8; ++j) {
                int b = bseg * 8 + j;
                unsigned doff = (unsigned)((b * 128 +
                    ((k4c & ~7) | ((k4c & 7) ^ (b & 7)))) * 16);
                unsigned soff = (unsigned)((b * 128 + k4c) * 16);
                CP_ASYNC16(sb2 + doff, s2 + soff);
            }
            CP_COMMIT();
#pragma unroll
            for (int j = 0; j < 8; ++j) {
                int b = bseg * 8 + j;
                unsigned doff = (unsigned)((b * 128 +
                    ((k4c & ~7) | ((k4c & 7) ^ (b & 7)))) * 16);
                unsigned soff = (unsigned)((b * 128 + k4c) * 16);
                CP_ASYNC16(sb3 + doff, s3 + soff);
            }
            CP_COMMIT();
        }
        // xp prefetch for layer-1 cells
        float xg0 = 0.f, xg1 = 0.f, xg2 = 0.f, xg3 = 0.f;
        if (v1 && tid < 128) {
            const float* xb = xp + (cb * TT + slot) * G4 + cunit;
            xg0 = __ldg(xb);
            xg1 = __ldg(xb + HH);
            xg2 = __ldg(xb + 2 * HH);
            xg3 = __ldg(xb + 3 * HH);
        }

        // ---- phase A : layer 1 (K=512, ng=16) ----
        CP_WAIT(2);
        __syncthreads();
        if (v1) {
            gphase(acc, a_w0, a_w1, hA, swz, 16);
            store_part(part, acc, ks, rg, bp);
        }
        __syncthreads();
        if (v1 && tid < 128) {
            float4 g = cell_sum(part, cu, cb);
            g.x += xg0; g.y += xg1; g.z += xg2; g.w += xg3;
            float hv = lstm_cell(g, c1);
            __stcg(&g_hb1[wrp][cb * HH + cunit], hv);
        }
        CP_WAIT(1);
        __syncthreads();

        // ---- phase B : layer 2 (K=1024, ng=32) ----
        if (v2) {
            gphase(acc, b_w0, b_w1, hB, swz, 32);
            store_part(part, acc, ks, rg, bp);
        }
        __syncthreads();
        if (v2 && tid < 128) {
            float4 g = cell_sum(part, cu, cb);
            g.x += bias2[0]; g.y += bias2[1]; g.z += bias2[2]; g.w += bias2[3];
            float hv = lstm_cell(g, c2);
            __stcg(&g_hb2[wrp][cb * HH + cunit], hv);
        }
        CP_WAIT(0);
        __syncthreads();

        // ---- phase C : layer 3 (K=1024, ng=32) ----
        if (v3) {
            gphase(acc, c_w0, c_w1, hC, swz, 32);
            store_part(part, acc, ks, rg, bp);
        }
        __syncthreads();
        if (v3 && tid < 128) {
            float4 g = cell_sum(part, cu, cb);
            g.x += bias3[0]; g.y += bias3[1]; g.z += bias3[2]; g.w += bias3[3];
            float hv = lstm_cell(g, c3);
            __stcg(&g_hb3[wrp][cb * HH + cunit], hv);
            h3sum += hv;
        }

        grid_bar();
    }
    if (tid < 128)
        g_feat[cb * HH + cunit] = h3sum * (1.f / 512.f);
}

// --------------------------------- head ------------------------------------
__global__ __launch_bounds__(64) void head_kernel(
    const float* __restrict__ hw, const float* __restrict__ hb,
    float* __restrict__ outp)
{
    const int c = blockIdx.x, b = blockIdx.y;
    float s = 0.f;
    for (int k = threadIdx.x; k < HH; k += 64)
        s += g_feat[b * HH + k] * hw[c * HH + k];
    __shared__ float red[2];
#pragma unroll
    for (int o = 16; o; o >>= 1) s += __shfl_down_sync(0xffffffffu, s, o);
    if ((threadIdx.x & 31) == 0) red[threadIdx.x >> 5] = s;
    __syncthreads();
    if (threadIdx.x == 0) outp[b * NCLS + c] = red[0] + red[1] + hb[c];
}

// ------------------------------ launcher -----------------------------------
extern "C" void kernel_launch(void* const* d_in, const int* in_sizes, int n_in,
                              void* d_out, int out_size)
{
    const float* x_emg  = (const float*)d_in[0];
    const float* conv_w = (const float*)d_in[1];
    const float* gamma  = (const float*)d_in[2];
    const float* beta   = (const float*)d_in[3];
    const float *w_ih[3], *w_hh[3], *bi[3], *head_w, *head_b;

    if (in_sizes[4] == 4 * HH * FF) {          // signature order
        for (int l = 0; l < 3; ++l) {
            w_ih[l] = (const float*)d_in[4 + 3 * l];
            w_hh[l] = (const float*)d_in[5 + 3 * l];
            bi[l]   = (const float*)d_in[6 + 3 * l];
        }
        head_w = (const float*)d_in[13];
        head_b = (const float*)d_in[14];
    } else {                                    // dict order
        head_w = (const float*)d_in[4];
        head_b = (const float*)d_in[5];
        for (int l = 0; l < 3; ++l) {
            w_ih[l] = (const float*)d_in[6 + 3 * l];
            w_hh[l] = (const float*)d_in[7 + 3 * l];
            bi[l]   = (const float*)d_in[8 + 3 * l];
        }
    }
    float* out = (float*)d_out;

    cudaFuncSetAttribute(conv_kernel,
        cudaFuncAttributeMaxDynamicSharedMemorySize, CONV_SMEM);
    cudaFuncSetAttribute(fused_rec_kernel,
        cudaFuncAttributeMaxDynamicSharedMemorySize, FSMEM);

    float* g_xp_p;   cudaGetSymbolAddress((void**)&g_xp_p, g_xp);
    float* g_xt_p;   cudaGetSymbolAddress((void**)&g_xt_p, g_xt);

    conv_kernel<<<dim3(TT / 128, BB), 256, CONV_SMEM>>>(x_emg, conv_w);
    gn_stats_kernel<<<BB * GG, 256>>>();
    gn_apply_kernel<<<dim3(TT / 32, FF / 32, BB), 256>>>(gamma, beta);

    gemm_kernel<<<dim3(G4 / 64, BB * TT / 64), 256>>>(
        g_xt_p, w_ih[0], bi[0], g_xp_p, FF);

    zero_h_kernel<<<128, 256>>>();
    fused_rec_kernel<<<RNB, 512, FSMEM>>>(
        g_xp_p, w_hh[0], w_ih[1], w_hh[1], bi[1], w_ih[2], w_hh[2], bi[2]);

    head_kernel<<<dim3(NCLS, BB), 64>>>(head_w, head_b, out);
}

// round 12
// speedup vs baseline: 1.4235x; 1.4235x over previous
#include <cuda_runtime.h>
#include <math.h>

typedef unsigned long long ull;

#define BB   32
#define CIN  64
#define TT   512
#define FF   256
#define GG   8
#define HH   512
#define G4   2048
#define NCLS 50
#define RNB  128
#define NSLOT (TT + 2)
#define PSZ  (16 * 16 * 34)

// ------------------------- scratch -----------------------------------------
__device__ float   g_conv[BB * FF * TT];
__device__ float   g_xt[BB * TT * FF];
__device__ float   g_xp[BB * TT * G4];
__device__ float   g_hb1[2][BB * HH];    // [parity][b*HH + unit]
__device__ float   g_hb2[2][BB * HH];
__device__ float   g_hb3[2][BB * HH];
__device__ float   g_feat[BB * HH];
__device__ float2  g_stat[BB * GG];
__device__ int     g_flags[RNB];
__device__ unsigned g_gen2;

// ------------------------- helpers -----------------------------------------
__device__ __forceinline__ void fma2(ull& d, ull a, ull b) {
    asm("fma.rn.f32x2 %0, %1, %2, %0;" : "+l"(d) : "l"(a), "l"(b));
}
union UF2 { ull u; float2 f; };
#define CP_ASYNC16(dst_u32, src_ptr) \
    asm volatile("cp.async.cg.shared.global [%0], [%1], 16;" \
                 :: "r"(dst_u32), "l"(src_ptr))
#define CP_COMMIT() asm volatile("cp.async.commit_group;")
#define CP_WAIT(n)  asm volatile("cp.async.wait_group " #n ";" ::: "memory")

// ------------------------------- conv1d ------------------------------------
#define CONV_SMEM ((64 * 136 + 8 * 64 * 9) * 4)
__global__ __launch_bounds__(256) void conv_kernel(
    const float* __restrict__ x, const float* __restrict__ w)
{
    extern __shared__ float sm[];
    float* xs = sm;
    float* ws = sm + 64 * 136;
    const int b   = blockIdx.y;
    const int t0  = blockIdx.x * 128;
    const int tid = threadIdx.x;

    for (int i = tid; i < 64 * 136; i += 256) {
        int c = i / 136, j = i - c * 136;
        int t = t0 - 4 + j;
        xs[i] = (t >= 0 && t < TT) ? x[(b * CIN + c) * TT + t] : 0.f;
    }
    const int lane = tid & 31;
    const int wf   = tid >> 5;
    const int tl   = lane * 4;

    for (int fc = 0; fc < FF; fc += 8) {
        __syncthreads();
        for (int i = tid; i < 8 * 64 * 9; i += 256)
            ws[i] = w[fc * 64 * 9 + i];
        __syncthreads();
        const int f = fc + wf;
        float a0 = 0.f, a1 = 0.f, a2 = 0.f, a3 = 0.f;
        for (int c = 0; c < 64; ++c) {
            const float* xr = &xs[c * 136 + tl];
            const float* wr = &ws[(wf * 64 + c) * 9];
            float4 p0 = *(const float4*)(xr);
            float4 p1 = *(const float4*)(xr + 4);
            float4 p2 = *(const float4*)(xr + 8);
            float xv[12] = {p0.x, p0.y, p0.z, p0.w, p1.x, p1.y, p1.z, p1.w,
                            p2.x, p2.y, p2.z, p2.w};
#pragma unroll
            for (int k = 0; k < 9; ++k) {
                float wk = wr[k];
                a0 += wk * xv[k];
                a1 += wk * xv[k + 1];
                a2 += wk * xv[k + 2];
                a3 += wk * xv[k + 3];
            }
        }
        *(float4*)&g_conv[(b * FF + f) * TT + t0 + tl] =
            make_float4(a0, a1, a2, a3);
    }
}

// ------------------------------ groupnorm -----------------------------------
__global__ __launch_bounds__(256) void gn_stats_kernel()
{
    const int b = blockIdx.x >> 3, g = blockIdx.x & 7;
    __shared__ float ssum[256], ssq[256];
    const int tid = threadIdx.x;
    const float* base = g_conv + (b * FF + g * 32) * TT;
    float s = 0.f, q = 0.f;
    for (int i = tid; i < 32 * TT; i += 256) {
        float v = base[i];
        s += v; q += v * v;
    }
    ssum[tid] = s; ssq[tid] = q;
    __syncthreads();
    for (int o = 128; o > 0; o >>= 1) {
        if (tid < o) { ssum[tid] += ssum[tid + o]; ssq[tid] += ssq[tid + o]; }
        __syncthreads();
    }
    if (tid == 0) {
        float mean = ssum[0] * (1.f / 16384.f);
        float var  = ssq[0] * (1.f / 16384.f) - mean * mean;
        g_stat[b * GG + g] = make_float2(mean, rsqrtf(var + 1e-5f));
    }
}

__global__ __launch_bounds__(256) void gn_apply_kernel(
    const float* __restrict__ gamma, const float* __restrict__ beta)
{
    __shared__ float tile[32][33];
    const int b  = blockIdx.z;
    const int f0 = blockIdx.y * 32;
    const int t0 = blockIdx.x * 32;
    const int tx = threadIdx.x & 31, ty = threadIdx.x >> 5;
#pragma unroll
    for (int j = 0; j < 4; ++j) {
        int f = f0 + ty + j * 8;
        float2 st = g_stat[b * GG + (f >> 5)];
        float v = g_conv[(b * FF + f) * TT + t0 + tx];
        v = (v - st.x) * st.y * gamma[f] + beta[f];
        tile[ty + j * 8][tx] = fmaxf(v, 0.f);
    }
    __syncthreads();
#pragma unroll
    for (int j = 0; j < 4; ++j) {
        int t = t0 + ty + j * 8;
        g_xt[(b * TT + t) * FF + f0 + tx] = tile[tx][ty + j * 8];
    }
}

// --------------------- projection GEMM (layer 1) ----------------------------
__global__ __launch_bounds__(256) void gemm_kernel(
    const float* __restrict__ A, const float* __restrict__ Bm,
    const float* __restrict__ bias, float* __restrict__ C, int Ka)
{
    __shared__ float As[16][64];
    __shared__ float Bs[16][64];
    const int bm = blockIdx.y * 64, bn = blockIdx.x * 64;
    const int tid = threadIdx.x;
    const int lm  = tid >> 2;
    const int lk4 = (tid & 3) * 4;
    const int tm  = (tid & 15) * 4;
    const int tn  = (tid >> 4) * 4;

    float acc[4][4];
#pragma unroll
    for (int i = 0; i < 4; ++i)
#pragma unroll
        for (int j = 0; j < 4; ++j) acc[i][j] = 0.f;

    for (int ko = 0; ko < Ka; ko += 16) {
        float4 av = *(const float4*)&A[(bm + lm) * Ka + ko + lk4];
        float4 bv = *(const float4*)&Bm[(bn + lm) * Ka + ko + lk4];
        __syncthreads();
        As[lk4 + 0][lm] = av.x; As[lk4 + 1][lm] = av.y;
        As[lk4 + 2][lm] = av.z; As[lk4 + 3][lm] = av.w;
        Bs[lk4 + 0][lm] = bv.x; Bs[lk4 + 1][lm] = bv.y;
        Bs[lk4 + 2][lm] = bv.z; Bs[lk4 + 3][lm] = bv.w;
        __syncthreads();
#pragma unroll
        for (int k = 0; k < 16; ++k) {
            float4 a4 = *(const float4*)&As[k][tm];
            float4 b4 = *(const float4*)&Bs[k][tn];
            float am[4] = {a4.x, a4.y, a4.z, a4.w};
            float bn4[4] = {b4.x, b4.y, b4.z, b4.w};
#pragma unroll
            for (int i = 0; i < 4; ++i)
#pragma unroll
                for (int j = 0; j < 4; ++j) acc[i][j] += am[i] * bn4[j];
        }
    }
#pragma unroll
    for (int i = 0; i < 4; ++i) {
        int row = bm + tm + i;
#pragma unroll
        for (int j = 0; j < 4; ++j)
            C[row * G4 + bn + tn + j] = acc[i][j] + bias[bn + tn + j];
    }
}

// --------------- zero h buffers + reset barrier state -----------------------
__global__ void zero_h_kernel()
{
    int i = blockIdx.x * 256 + threadIdx.x;   // grid 128 -> 32768 (both parities)
    ((float*)g_hb1)[i] = 0.f;
    ((float*)g_hb2)[i] = 0.f;
    ((float*)g_hb3)[i] = 0.f;
    if (blockIdx.x == 0) {
        if (threadIdx.x < RNB) g_flags[threadIdx.x] = 0;
        if (threadIdx.x == 0)  g_gen2 = 0u;
    }
}

// ------------------------- flag-array grid barrier --------------------------
// Distinct flag per block (no same-address atomic serialization); block 0
// gathers with 128 threads, publishes one release word.
__device__ __forceinline__ void grid_bar2(int slot)
{
    __syncthreads();
    const int tid = threadIdx.x;
    if (tid == 0) {
        __threadfence();
        ((volatile int*)g_flags)[blockIdx.x] = slot + 1;
    }
    if (blockIdx.x == 0) {
        if (tid < RNB)
            while (((volatile int*)g_flags)[tid] <= slot) __nanosleep(32);
        __syncthreads();
        if (tid == 0) {
            __threadfence();
            *((volatile unsigned*)&g_gen2) = (unsigned)(slot + 1);
        }
    } else {
        if (tid == 0)
            while (*((volatile unsigned*)&g_gen2) <= (unsigned)slot)
                __nanosleep(32);
    }
    __syncthreads();
}

// -------------------- per-thread GEMM slice (R7, proven) --------------------
__device__ __forceinline__ void gphase(ull acc[8][2],
    const float* __restrict__ w0, const float* __restrict__ w1,
    const float* hr0, const float* hr1, int swz, int nk4)
{
#pragma unroll
    for (int i = 0; i < 8; ++i) { acc[i][0] = 0ull; acc[i][1] = 0ull; }
#pragma unroll 4
    for (int l = 0; l < nk4; ++l) {
        const int lp = ((l & ~7) | ((l & 7) ^ swz)) * 4;
        ulonglong2 h0 = *(const ulonglong2*)(hr0 + lp);
        ulonglong2 h1 = *(const ulonglong2*)(hr1 + lp);
#pragma unroll
        for (int i = 0; i < 4; ++i) {
            ulonglong2 wv = __ldg((const ulonglong2*)(w0 + i * 512 + l * 4));
            fma2(acc[i][0], wv.x, h0.x); fma2(acc[i][0], wv.y, h0.y);
            fma2(acc[i][1], wv.x, h1.x); fma2(acc[i][1], wv.y, h1.y);
        }
#pragma unroll
        for (int i = 0; i < 4; ++i) {
            ulonglong2 wv = __ldg((const ulonglong2*)(w1 + i * 512 + l * 4));
            fma2(acc[4 + i][0], wv.x, h0.x); fma2(acc[4 + i][0], wv.y, h0.y);
            fma2(acc[4 + i][1], wv.x, h1.x); fma2(acc[4 + i][1], wv.y, h1.y);
        }
    }
}

__device__ __forceinline__ void store_part(float* part, ull acc[8][2],
                                           int ks, int rg, int bq)
{
#pragma unroll
    for (int i = 0; i < 8; ++i) {
        UF2 t0, t1; t0.u = acc[i][0]; t1.u = acc[i][1];
        *(float2*)&part[(ks * 16 + rg * 8 + i) * 34 + 2 * bq] =
            make_float2(t0.f.x + t0.f.y, t1.f.x + t1.f.y);
    }
}

__device__ __forceinline__ float4 cell_sum(const float* part, int cu, int cb)
{
    float4 s = make_float4(0.f, 0.f, 0.f, 0.f);
#pragma unroll
    for (int k = 0; k < 16; ++k) {
        const float* pb = part + (k * 16) * 34 + cb;
        s.x += pb[(0 + cu) * 34];
        s.y += pb[(4 + cu) * 34];
        s.z += pb[(8 + cu) * 34];
        s.w += pb[(12 + cu) * 34];
    }
    return s;
}

__device__ __forceinline__ float lstm_cell(float4 g, float& c)
{
    float ig = 1.f / (1.f + __expf(-g.x));
    float fg = 1.f / (1.f + __expf(-g.y));
    float gv = tanhf(g.z);
    float og = 1.f / (1.f + __expf(-g.w));
    c = fg * c + ig * gv;
    return og * tanhf(c);
}

// ------------------- fused 3-layer wavefront recurrence ---------------------
// smem: buf1/2/3 [32 b][512 k] (64KB each, pair-swizzled) + part (34KB)
#define FSMEM ((3 * HH * BB + PSZ) * 4)
__global__ __launch_bounds__(512, 1) void fused_rec_kernel(
    const float* __restrict__ xp,
    const float* __restrict__ whh1,
    const float* __restrict__ wih2, const float* __restrict__ whh2,
    const float* __restrict__ b2,
    const float* __restrict__ wih3, const float* __restrict__ whh3,
    const float* __restrict__ b3)
{
    extern __shared__ float sm[];
    float* buf1 = sm;
    float* buf2 = sm + HH * BB;
    float* buf3 = sm + 2 * HH * BB;
    float* part = sm + 3 * HH * BB;

    const int tid = threadIdx.x;
    const int ks  = tid >> 5;          // warp = k-slice 0..15
    const int rg  = (tid >> 4) & 1;    // gate-pair
    const int bq  = tid & 15;          // batch pair
    const int swz = bq & 7;
    const int b0  = 2 * bq;
    const int u4  = blockIdx.x * 4;

    // weight row bases (all matrices K=512)
    const int g0r = (2 * rg) * HH + u4;
    const int g1r = (2 * rg + 1) * HH + u4;
    const float* a_w0 = whh1 + g0r * 512 + ks * 32;
    const float* a_w1 = whh1 + g1r * 512 + ks * 32;
    const float* wBm  = (ks < 8) ? wih2 : whh2;
    const float* wCm  = (ks < 8) ? wih3 : whh3;
    const int koff = (ks & 7) * 64;
    const float* b_w0 = wBm + g0r * 512 + koff;
    const float* b_w1 = wBm + g1r * 512 + koff;
    const float* c_w0 = wCm + g0r * 512 + koff;
    const float* c_w1 = wCm + g1r * 512 + koff;

    // h smem slice bases (row b0; row b0+1 at +512)
    const float* hA = buf1 + b0 * 512 + ks * 32;
    const float* hB = ((ks < 8) ? buf1 : buf2) + b0 * 512 + koff;
    const float* hC = ((ks < 8) ? buf2 : buf3) + b0 * 512 + koff;

    // cell mapping (tid < 128)
    const int cu = tid >> 5;
    const int cb = tid & 31;
    const int cunit = u4 + cu;
    float c1 = 0.f, c2 = 0.f, c3 = 0.f, h3sum = 0.f;
    float bias2[4], bias3[4];
    if (tid < 128) {
#pragma unroll
        for (int g = 0; g < 4; ++g) {
            bias2[g] = b2[g * HH + cunit];
            bias3[g] = b3[g * HH + cunit];
        }
    }

    // staging: thread copies granule k4c for 8 b-rows
    const int k4c  = tid & 127;
    const int bseg = tid >> 7;      // 0..3
    const unsigned sb1 = (unsigned)__cvta_generic_to_shared(buf1);
    const unsigned sb2 = (unsigned)__cvta_generic_to_shared(buf2);
    const unsigned sb3 = (unsigned)__cvta_generic_to_shared(buf3);

    ull acc[8][2];

    for (int slot = 0; slot < NSLOT; ++slot) {
        const int rdp = (slot + 1) & 1;
        const int wrp = slot & 1;
        const bool v1 = slot < TT;
        const bool v2 = (slot >= 1) && (slot < TT + 1);
        const bool v3 = slot >= 2;

        // ---- async stage h1/h2/h3 (one commit group per buffer) ----
        {
            const char* s1 = (const char*)(g_hb1[rdp]);
            const char* s2 = (const char*)(g_hb2[rdp]);
            const char* s3 = (const char*)(g_hb3[rdp]);
#pragma unroll
            for (int j = 0; j < 8; ++j) {
                int b = bseg * 8 + j;
                unsigned doff = (unsigned)((b * 128 + (k4c ^ ((b >> 1) & 7))) * 16);
                unsigned soff = (unsigned)((b * 128 + k4c) * 16);
                CP_ASYNC16(sb1 + doff, s1 + soff);
            }
            CP_COMMIT();
#pragma unroll
            for (int j = 0; j < 8; ++j) {
                int b = bseg * 8 + j;
                unsigned doff = (unsigned)((b * 128 + (k4c ^ ((b >> 1) & 7))) * 16);
                unsigned soff = (unsigned)((b * 128 + k4c) * 16);
                CP_ASYNC16(sb2 + doff, s2 + soff);
            }
            CP_COMMIT();
#pragma unroll
            for (int j = 0; j < 8; ++j) {
                int b = bseg * 8 + j;
                unsigned doff = (unsigned)((b * 128 + (k4c ^ ((b >> 1) & 7))) * 16);
                unsigned soff = (unsigned)((b * 128 + k4c) * 16);
                CP_ASYNC16(sb3 + doff, s3 + soff);
            }
            CP_COMMIT();
        }
        float xg0 = 0.f, xg1 = 0.f, xg2 = 0.f, xg3 = 0.f;
        if (v1 && tid < 128) {
            const float* xb = xp + (cb * TT + slot) * G4 + cunit;
            xg0 = __ldg(xb);
            xg1 = __ldg(xb + HH);
            xg2 = __ldg(xb + 2 * HH);
            xg3 = __ldg(xb + 3 * HH);
        }

        // ---- phase A : layer 1 ----
        CP_WAIT(2);
        __syncthreads();
        if (v1) {
            gphase(acc, a_w0, a_w1, hA, hA + 512, swz, 8);
            store_part(part, acc, ks, rg, bq);
        }
        __syncthreads();
        if (v1 && tid < 128) {
            float4 g = cell_sum(part, cu, cb);
            g.x += xg0; g.y += xg1; g.z += xg2; g.w += xg3;
            float hv = lstm_cell(g, c1);
            __stcg(&g_hb1[wrp][cb * HH + cunit], hv);
        }
        CP_WAIT(1);
        __syncthreads();

        // ---- phase B : layer 2 ----
        if (v2) {
            gphase(acc, b_w0, b_w1, hB, hB + 512, swz, 16);
            store_part(part, acc, ks, rg, bq);
        }
        __syncthreads();
        if (v2 && tid < 128) {
            float4 g = cell_sum(part, cu, cb);
            g.x += bias2[0]; g.y += bias2[1]; g.z += bias2[2]; g.w += bias2[3];
            float hv = lstm_cell(g, c2);
            __stcg(&g_hb2[wrp][cb * HH + cunit], hv);
        }
        CP_WAIT(0);
        __syncthreads();

        // ---- phase C : layer 3 ----
        if (v3) {
            gphase(acc, c_w0, c_w1, hC, hC + 512, swz, 16);
            store_part(part, acc, ks, rg, bq);
        }
        __syncthreads();
        if (v3 && tid < 128) {
            float4 g = cell_sum(part, cu, cb);
            g.x += bias3[0]; g.y += bias3[1]; g.z += bias3[2]; g.w += bias3[3];
            float hv = lstm_cell(g, c3);
            __stcg(&g_hb3[wrp][cb * HH + cunit], hv);
            h3sum += hv;
        }

        grid_bar2(slot);
    }
    if (tid < 128)
        g_feat[cb * HH + cunit] = h3sum * (1.f / 512.f);
}

// --------------------------------- head ------------------------------------
__global__ __launch_bounds__(64) void head_kernel(
    const float* __restrict__ hw, const float* __restrict__ hb,
    float* __restrict__ outp)
{
    const int c = blockIdx.x, b = blockIdx.y;
    float s = 0.f;
    for (int k = threadIdx.x; k < HH; k += 64)
        s += g_feat[b * HH + k] * hw[c * HH + k];
    __shared__ float red[2];
#pragma unroll
    for (int o = 16; o; o >>= 1) s += __shfl_down_sync(0xffffffffu, s, o);
    if ((threadIdx.x & 31) == 0) red[threadIdx.x >> 5] = s;
    __syncthreads();
    if (threadIdx.x == 0) outp[b * NCLS + c] = red[0] + red[1] + hb[c];
}

// ------------------------------ launcher -----------------------------------
extern "C" void kernel_launch(void* const* d_in, const int* in_sizes, int n_in,
                              void* d_out, int out_size)
{
    const float* x_emg  = (const float*)d_in[0];
    const float* conv_w = (const float*)d_in[1];
    const float* gamma  = (const float*)d_in[2];
    const float* beta   = (const float*)d_in[3];
    const float *w_ih[3], *w_hh[3], *bi[3], *head_w, *head_b;

    if (in_sizes[4] == 4 * HH * FF) {          // signature order
        for (int l = 0; l < 3; ++l) {
            w_ih[l] = (const float*)d_in[4 + 3 * l];
            w_hh[l] = (const float*)d_in[5 + 3 * l];
            bi[l]   = (const float*)d_in[6 + 3 * l];
        }
        head_w = (const float*)d_in[13];
        head_b = (const float*)d_in[14];
    } else {                                    // dict order
        head_w = (const float*)d_in[4];
        head_b = (const float*)d_in[5];
        for (int l = 0; l < 3; ++l) {
            w_ih[l] = (const float*)d_in[6 + 3 * l];
            w_hh[l] = (const float*)d_in[7 + 3 * l];
            bi[l]   = (const float*)d_in[8 + 3 * l];
        }
    }
    float* out = (float*)d_out;

    cudaFuncSetAttribute(conv_kernel,
        cudaFuncAttributeMaxDynamicSharedMemorySize, CONV_SMEM);
    cudaFuncSetAttribute(fused_rec_kernel,
        cudaFuncAttributeMaxDynamicSharedMemorySize, FSMEM);

    float* g_xp_p;   cudaGetSymbolAddress((void**)&g_xp_p, g_xp);
    float* g_xt_p;   cudaGetSymbolAddress((void**)&g_xt_p, g_xt);

    conv_kernel<<<dim3(TT / 128, BB), 256, CONV_SMEM>>>(x_emg, conv_w);
    gn_stats_kernel<<<BB * GG, 256>>>();
    gn_apply_kernel<<<dim3(TT / 32, FF / 32, BB), 256>>>(gamma, beta);

    gemm_kernel<<<dim3(G4 / 64, BB * TT / 64), 256>>>(
        g_xt_p, w_ih[0], bi[0], g_xp_p, FF);

    zero_h_kernel<<<128, 256>>>();
    fused_rec_kernel<<<RNB, 512, FSMEM>>>(
        g_xp_p, w_hh[0], w_ih[1], w_hh[1], bi[1], w_ih[2], w_hh[2], bi[2]);

    head_kernel<<<dim3(NCLS, BB), 64>>>(head_w, head_b, out);
}